// round 6
// baseline (speedup 1.0000x reference)
#include <cuda_runtime.h>
#include <cuda_fp16.h>
#include <math.h>
#include <cstdint>

// ---------------------------------------------------------------------------
// Problem constants
// ---------------------------------------------------------------------------
#define C_      32
#define B_      8
#define INCH    201          // K*C*2 + K*K
#define KH      208          // K padded to 13 x 16 (halves)
#define KST     13           // k16 steps
#define NCH     72           // N per chunk (exactly 2 channels x 36)
#define NCHUNKS 16           // 1152 / 72
#define FSTR_H  216          // feat/B row stride in halves (27 x 16B, coprime 8)
#define FSTR_B  432          // ... in bytes
#define THREADS 512

// SMEM layout (bytes)
#define XS_FL    (32*33*17)                 // 17952 floats
#define XS_OFF   0
#define BIAS_OFF (XS_FL*4)                  // 71808
#define FEAT_OFF (BIAS_OFF + 1152*4)        // 76416
#define B0_OFF   (FEAT_OFF + 128*FSTR_B)    // 131712
#define BBYTES   (NCH*FSTR_B)               // 31104
#define B1_OFF   (B0_OFF + BBYTES)          // 162816
#define YB_OFF   (B1_OFF + BBYTES)          // 193920
#define YSTR     74
#define SMEM_BYTES (YB_OFF + 128*YSTR*4)    // 231808 (< 232448 max)

// ---------------------------------------------------------------------------
// Static scratch (no allocations)
// ---------------------------------------------------------------------------
__device__ __half g_wh[1152 * KH];   // BN-folded fp16 weights, K-padded
__device__ float  g_bias[1152];

// ---------------------------------------------------------------------------
// PTX helpers (sm_103 BASE features only: ldmatrix / mma.sync / cp.async)
// ---------------------------------------------------------------------------
__device__ __forceinline__ uint32_t su32(const void* p) {
    uint32_t a;
    asm("{ .reg .u64 t; cvta.to.shared.u64 t, %1; cvt.u32.u64 %0, t; }" : "=r"(a) : "l"(p));
    return a;
}
__device__ __forceinline__ void ldsm4(uint32_t* r, uint32_t a) {
    asm volatile("ldmatrix.sync.aligned.m8n8.x4.shared.b16 {%0,%1,%2,%3}, [%4];"
                 : "=r"(r[0]), "=r"(r[1]), "=r"(r[2]), "=r"(r[3]) : "r"(a));
}
__device__ __forceinline__ void ldsm2(uint32_t* r, uint32_t a) {
    asm volatile("ldmatrix.sync.aligned.m8n8.x2.shared.b16 {%0,%1}, [%2];"
                 : "=r"(r[0]), "=r"(r[1]) : "r"(a));
}
__device__ __forceinline__ void mma16816(float* c, const uint32_t* a, const uint32_t* b) {
    asm volatile("mma.sync.aligned.m16n8k16.row.col.f32.f16.f16.f32 "
                 "{%0,%1,%2,%3}, {%4,%5,%6,%7}, {%8,%9}, {%0,%1,%2,%3};"
                 : "+f"(c[0]), "+f"(c[1]), "+f"(c[2]), "+f"(c[3])
                 : "r"(a[0]), "r"(a[1]), "r"(a[2]), "r"(a[3]), "r"(b[0]), "r"(b[1]));
}
__device__ __forceinline__ void cpasync16(uint32_t dst, const void* src) {
    asm volatile("cp.async.cg.shared.global [%0], [%1], 16;" :: "r"(dst), "l"(src));
}
__device__ __forceinline__ void cpcommit() { asm volatile("cp.async.commit_group;"); }
__device__ __forceinline__ void cpwait0()  { asm volatile("cp.async.wait_group 0;" ::: "memory"); }

// ---------------------------------------------------------------------------
// Repack: fold BN into conv_w, convert fp16, pad K 201->208
// ---------------------------------------------------------------------------
__global__ void repack_kernel(const float* __restrict__ w,
                              const float* __restrict__ gamma,
                              const float* __restrict__ beta,
                              const float* __restrict__ mean,
                              const float* __restrict__ var) {
    int m = blockIdx.x;
    float sc = gamma[m] * rsqrtf(var[m] + 1e-5f);
    if (threadIdx.x == 0) g_bias[m] = beta[m] - mean[m] * sc;
    for (int k = threadIdx.x; k < KH; k += blockDim.x) {
        float v = (k < INCH) ? w[m * INCH + k] * sc : 0.f;
        g_wh[m * KH + k] = __float2half_rn(v);
    }
}

// Stage one 72-row N-chunk of fp16 weights into SMEM [n][k], stride 216 halves
__device__ __forceinline__ void stage_b(uint32_t bufs, int n0, int tid) {
    for (int e = tid; e < NCH * 26; e += THREADS) {
        int r = e / 26, q = e - r * 26;
        cpasync16(bufs + r * FSTR_B + q * 16,
                  g_wh + (size_t)(n0 + r) * KH + q * 8);
    }
}

// ---------------------------------------------------------------------------
// One N-chunk GEMM: warp covers M=16 rows x NT n-tiles over K=208.
// ---------------------------------------------------------------------------
template <int NT>
__device__ __forceinline__ void gemm_chunk(uint32_t fbase, uint32_t bbase,
                                           int m0, int lane, float acc[][4]) {
    #pragma unroll
    for (int s = 0; s < KST; ++s) {
        uint32_t a[4];
        ldsm4(a, fbase + (uint32_t)(m0 + (lane & 15)) * FSTR_B
                 + s * 32 + (lane >> 4) * 16);
        uint32_t bf[NT][2];
        #pragma unroll
        for (int pq = 0; pq < NT / 2; ++pq) {
            uint32_t ad = bbase
                        + (uint32_t)((pq * 2 + (lane >> 4)) * 8 + (lane & 7)) * FSTR_B
                        + s * 32 + ((lane >> 3) & 1) * 16;
            uint32_t t4[4];
            ldsm4(t4, ad);
            bf[2 * pq][0] = t4[0]; bf[2 * pq][1] = t4[1];
            bf[2 * pq + 1][0] = t4[2]; bf[2 * pq + 1][1] = t4[3];
        }
        if (NT & 1) {
            uint32_t ad = bbase + (uint32_t)((NT - 1) * 8 + (lane & 7)) * FSTR_B
                        + s * 32 + ((lane >> 3) & 1) * 16;
            ldsm2(bf[NT - 1], ad);
        }
        #pragma unroll
        for (int nt = 0; nt < NT; ++nt)
            mma16816(acc[nt], a, bf[nt]);
    }
}

// ---------------------------------------------------------------------------
// Main fused kernel: CTA = 128 pixels (16 oy x 8 ox) of one batch image
// ---------------------------------------------------------------------------
__global__ __launch_bounds__(THREADS, 1)
void revo_hmma(const float* __restrict__ x, float* __restrict__ out) {
    extern __shared__ char smem[];
    float*  xs     = (float*)(smem + XS_OFF);
    float*  bias_s = (float*)(smem + BIAS_OFF);
    __half* feat   = (__half*)(smem + FEAT_OFF);
    float*  ybuf   = (float*)(smem + YB_OFF);
    float*  scr    = ybuf;                   // cm partials, pre-loop only
    const uint32_t sb = su32(smem);

    const int tid = threadIdx.x, lane = tid & 31, wid = tid >> 5;
    const int b = blockIdx.z, oy0 = blockIdx.y * 16, ox0 = blockIdx.x * 8;

    // stage weight chunk 0 early (overlaps x-tile load)
    stage_b(sb + B0_OFF, 0, tid);
    cpcommit();

    // ---- x tile [32][33][17], zero-padded halo + bias ----
    const float* xb = x + (size_t)b * C_ * 16384;
    for (int e = tid; e < XS_FL; e += THREADS) {
        int c = e / 561, rem = e - c * 561;
        int yy = rem / 17, xx = rem - yy * 17;
        int iy = 2 * oy0 - 1 + yy, ix = 2 * ox0 - 1 + xx;
        float v = 0.f;
        if ((unsigned)iy < 128u && (unsigned)ix < 128u) v = xb[c * 16384 + iy * 128 + ix];
        xs[e] = v;
    }
    for (int e = tid; e < 1152; e += THREADS) bias_s[e] = g_bias[e];
    __syncthreads();

    // ---- feat build, parallel over (pixel, 8-channel group) ----
    {
        const int p = tid & 127, cg = tid >> 7;
        const int oyl = p >> 3, oxl = p & 7;
        const int pb = (2 * oyl) * 17 + 2 * oxl;
        __half* fr = feat + p * FSTR_H;
        float cm[9];
        #pragma unroll
        for (int kk = 0; kk < 9; ++kk) cm[kk] = -3.402823466e38f;
        #pragma unroll
        for (int cc = 0; cc < 8; ++cc) {
            const int c = cg * 8 + cc;
            const float* xc = xs + c * 561 + pb;
            float ph[9];
            #pragma unroll
            for (int ki = 0; ki < 3; ++ki)
                #pragma unroll
                for (int kj = 0; kj < 3; ++kj) ph[ki * 3 + kj] = xc[ki * 17 + kj];
            #pragma unroll
            for (int kk = 0; kk < 9; ++kk) cm[kk] = fmaxf(cm[kk], ph[kk]);
            #pragma unroll
            for (int j = 0; j < 3; ++j)   // max over kernel rows
                fr[9 + c * 3 + j] =
                    __float2half_rn(fmaxf(fmaxf(ph[j], ph[3 + j]), ph[6 + j]));
            #pragma unroll
            for (int i = 0; i < 3; ++i)   // max over kernel cols
                fr[105 + c * 3 + i] =
                    __float2half_rn(fmaxf(fmaxf(ph[3 * i], ph[3 * i + 1]), ph[3 * i + 2]));
        }
        #pragma unroll
        for (int kk = 0; kk < 9; ++kk) scr[p * 48 + cg * 12 + kk] = cm[kk];
    }
    __syncthreads();
    // 4-way reduce channel-max partials -> feat[0..8], zero-pad 201..207
    for (int e = tid; e < 128 * 9; e += THREADS) {
        int p = e / 9, kk = e - p * 9;
        float m = fmaxf(fmaxf(scr[p * 48 + kk],      scr[p * 48 + 12 + kk]),
                        fmaxf(scr[p * 48 + 24 + kk], scr[p * 48 + 36 + kk]));
        feat[p * FSTR_H + kk] = __float2half_rn(m);
    }
    if (tid < 128) {
        #pragma unroll
        for (int k = INCH; k < KH; ++k)
            feat[tid * FSTR_H + k] = __ushort_as_half(0);
    }
    cpwait0();
    __syncthreads();

    // warp tiling: 8 M-groups (16 rows) x 2 N-groups (5 / 4 n-tiles of the 9)
    const int m0 = (wid >> 1) * 16;
    const int ngrp = wid & 1;
    const int tb = ngrp ? 5 : 0;            // n-tile base
    const int g = lane >> 2, tg = lane & 3;

    for (int t = 0; t < NCHUNKS; ++t) {
        const uint32_t bb = sb + ((t & 1) ? B1_OFF : B0_OFF);
        if (t + 1 < NCHUNKS) {              // prefetch next weight chunk
            stage_b(sb + (((t + 1) & 1) ? B1_OFF : B0_OFF), (t + 1) * NCH, tid);
        }
        cpcommit();

        float acc[5][4];
        #pragma unroll
        for (int i = 0; i < 5; ++i)
            #pragma unroll
            for (int k = 0; k < 4; ++k) acc[i][k] = 0.f;

        if (ngrp == 0) gemm_chunk<5>(sb + FEAT_OFF, bb, m0, lane, acc);
        else           gemm_chunk<4>(sb + FEAT_OFF, bb + 5 * 8 * FSTR_B, m0, lane, acc);

        // C frags -> ybuf[p][n]
        const int NTloc = ngrp ? 4 : 5;
        #pragma unroll
        for (int nt = 0; nt < 5; ++nt) {
            if (nt < NTloc) {
                int n = (tb + nt) * 8 + 2 * tg;
                *(float2*)(ybuf + (m0 + g) * YSTR + n) =
                    make_float2(acc[nt][0], acc[nt][1]);
                *(float2*)(ybuf + (m0 + g + 8) * YSTR + n) =
                    make_float2(acc[nt][2], acc[nt][3]);
            }
        }
        __syncthreads();

        // fused epilogue: thread = (pixel, channel-of-chunk, u-row)
        {
            const int p = tid >> 2, dc = (tid >> 1) & 1, u = tid & 1;
            const int oyl = p >> 3, oxl = p & 7;
            const int c = t * 2 + dc;
            const float* xc = xs + c * 561 + (2 * oyl) * 17 + 2 * oxl;
            float ph[9];
            #pragma unroll
            for (int ki = 0; ki < 3; ++ki)
                #pragma unroll
                for (int kj = 0; kj < 3; ++kj) ph[ki * 3 + kj] = xc[ki * 17 + kj];
            const float* yb = ybuf + p * YSTR + dc * 36 + u * 2;
            const float* bs = bias_s + t * NCH + dc * 36 + u * 2;
            float o0 = 0.f, o1 = 0.f;
            #pragma unroll
            for (int kk = 0; kk < 9; ++kk) {
                const float pv = ph[kk];
                o0 += pv * fmaxf(yb[kk * 4]     + bs[kk * 4],     0.f);
                o1 += pv * fmaxf(yb[kk * 4 + 1] + bs[kk * 4 + 1], 0.f);
            }
            const float inv9 = 1.f / 9.f;
            const size_t ob = ((size_t)(b * C_ + c) * 128 + 2 * (oy0 + oyl) + u) * 128
                            + 2 * (ox0 + oxl);
            *(float2*)(out + ob) = make_float2(o0 * inv9, o1 * inv9);
        }
        cpwait0();
        __syncthreads();
    }
}

// ---------------------------------------------------------------------------
extern "C" void kernel_launch(void* const* d_in, const int* in_sizes, int n_in,
                              void* d_out, int out_size) {
    const float* x   = (const float*)d_in[0];
    const float* cw  = (const float*)d_in[1];
    const float* gam = (const float*)d_in[2];
    const float* bet = (const float*)d_in[3];
    const float* mn  = (const float*)d_in[4];
    const float* vr  = (const float*)d_in[5];
    float* out       = (float*)d_out;

    cudaFuncSetAttribute(revo_hmma, cudaFuncAttributeMaxDynamicSharedMemorySize,
                         SMEM_BYTES);

    repack_kernel<<<1152, 128>>>(cw, gam, bet, mn, vr);
    dim3 grid(8, 4, B_);
    revo_hmma<<<grid, 512, SMEM_BYTES>>>(x, out);
}

// round 7
// speedup vs baseline: 1.2502x; 1.2502x over previous
#include <cuda_runtime.h>
#include <cuda_fp16.h>
#include <math.h>
#include <cstdint>

// ---------------------------------------------------------------------------
// Problem constants
// ---------------------------------------------------------------------------
#define C_      32
#define B_      8
#define INCH    201          // K*C*2 + K*K
#define KH      208          // K padded to 13 x 16 (halves)
#define KST     13           // k16 steps
#define NCH     72           // N per chunk (exactly 2 channels x 36)
#define NCHUNKS 16           // 1152 / 72
#define FSTR_H  216          // feat/B row stride in halves (27 x 16B, coprime 8)
#define FSTR_B  432          // ... in bytes
#define THREADS 256

// SMEM layout (bytes)
#define XS_FL    (32*33*17)                 // 17952 floats
#define XS_OFF   0
#define BIAS_OFF (XS_FL*4)                  // 71808
#define FEAT_OFF (BIAS_OFF + 1152*4)        // 76416
#define B0_OFF   (FEAT_OFF + 128*FSTR_B)    // 131712
#define BBYTES   (NCH*FSTR_B)               // 31104
#define B1_OFF   (B0_OFF + BBYTES)          // 162816
#define YB0_OFF  193920
#define YSTR_H2  37                         // ybuf pixel stride in half2
#define YB_BYTES (128*YSTR_H2*4)            // 18944
#define YB1_OFF  (YB0_OFF + YB_BYTES)       // 212864
#define SMEM_BYTES (YB1_OFF + YB_BYTES)     // 231808

// ---------------------------------------------------------------------------
// Static scratch (no allocations)
// ---------------------------------------------------------------------------
__device__ __half g_wh[1152 * KH];   // BN-folded fp16 weights, K-padded
__device__ float  g_bias[1152];

// ---------------------------------------------------------------------------
// PTX helpers (sm_103 BASE features only: ldmatrix / mma.sync / cp.async)
// ---------------------------------------------------------------------------
__device__ __forceinline__ uint32_t su32(const void* p) {
    uint32_t a;
    asm("{ .reg .u64 t; cvta.to.shared.u64 t, %1; cvt.u32.u64 %0, t; }" : "=r"(a) : "l"(p));
    return a;
}
__device__ __forceinline__ void ldsm4(uint32_t* r, uint32_t a) {
    asm volatile("ldmatrix.sync.aligned.m8n8.x4.shared.b16 {%0,%1,%2,%3}, [%4];"
                 : "=r"(r[0]), "=r"(r[1]), "=r"(r[2]), "=r"(r[3]) : "r"(a));
}
__device__ __forceinline__ void ldsm2(uint32_t* r, uint32_t a) {
    asm volatile("ldmatrix.sync.aligned.m8n8.x2.shared.b16 {%0,%1}, [%2];"
                 : "=r"(r[0]), "=r"(r[1]) : "r"(a));
}
__device__ __forceinline__ void mma16816(float* c, const uint32_t* a, const uint32_t* b) {
    asm volatile("mma.sync.aligned.m16n8k16.row.col.f32.f16.f16.f32 "
                 "{%0,%1,%2,%3}, {%4,%5,%6,%7}, {%8,%9}, {%0,%1,%2,%3};"
                 : "+f"(c[0]), "+f"(c[1]), "+f"(c[2]), "+f"(c[3])
                 : "r"(a[0]), "r"(a[1]), "r"(a[2]), "r"(a[3]), "r"(b[0]), "r"(b[1]));
}
__device__ __forceinline__ void cpasync16(uint32_t dst, const void* src) {
    asm volatile("cp.async.cg.shared.global [%0], [%1], 16;" :: "r"(dst), "l"(src));
}
__device__ __forceinline__ void cpcommit() { asm volatile("cp.async.commit_group;"); }
__device__ __forceinline__ void cpwait1()  { asm volatile("cp.async.wait_group 1;" ::: "memory"); }

// ---------------------------------------------------------------------------
// Repack: fold BN into conv_w, convert fp16, pad K 201->208
// ---------------------------------------------------------------------------
__global__ void repack_kernel(const float* __restrict__ w,
                              const float* __restrict__ gamma,
                              const float* __restrict__ beta,
                              const float* __restrict__ mean,
                              const float* __restrict__ var) {
    int m = blockIdx.x;
    float sc = gamma[m] * rsqrtf(var[m] + 1e-5f);
    if (threadIdx.x == 0) g_bias[m] = beta[m] - mean[m] * sc;
    for (int k = threadIdx.x; k < KH; k += blockDim.x) {
        float v = (k < INCH) ? w[m * INCH + k] * sc : 0.f;
        g_wh[m * KH + k] = __float2half_rn(v);
    }
}

// Stage one 72-row N-chunk of fp16 weights into SMEM [n][k], stride 216 halves
__device__ __forceinline__ void stage_b(uint32_t bufs, int n0, int tid) {
    for (int e = tid; e < NCH * 26; e += THREADS) {
        int r = e / 26, q = e - r * 26;
        cpasync16(bufs + r * FSTR_B + q * 16,
                  g_wh + (size_t)(n0 + r) * KH + q * 8);
    }
}

// ---------------------------------------------------------------------------
// One N-chunk GEMM: warp covers M=32 (2 mtiles) x NT n-tiles over K=208.
// ---------------------------------------------------------------------------
template <int NT>
__device__ __forceinline__ void gemm_chunk(uint32_t fbase, uint32_t bbase,
                                           int m0, int lane, float acc[][2][4]) {
    #pragma unroll
    for (int s = 0; s < KST; ++s) {
        uint32_t a[2][4];
        #pragma unroll
        for (int mt = 0; mt < 2; ++mt) {
            ldsm4(a[mt], fbase + (uint32_t)(m0 + mt * 16 + (lane & 15)) * FSTR_B
                         + s * 32 + (lane >> 4) * 16);
        }
        uint32_t bf[NT][2];
        #pragma unroll
        for (int pq = 0; pq < NT / 2; ++pq) {
            uint32_t ad = bbase
                        + (uint32_t)((pq * 2 + (lane >> 4)) * 8 + (lane & 7)) * FSTR_B
                        + s * 32 + ((lane >> 3) & 1) * 16;
            uint32_t t4[4];
            ldsm4(t4, ad);
            bf[2 * pq][0] = t4[0]; bf[2 * pq][1] = t4[1];
            bf[2 * pq + 1][0] = t4[2]; bf[2 * pq + 1][1] = t4[3];
        }
        if (NT & 1) {
            uint32_t ad = bbase + (uint32_t)((NT - 1) * 8 + (lane & 7)) * FSTR_B
                        + s * 32 + ((lane >> 3) & 1) * 16;
            ldsm2(bf[NT - 1], ad);
        }
        #pragma unroll
        for (int nt = 0; nt < NT; ++nt)
            #pragma unroll
            for (int mt = 0; mt < 2; ++mt)
                mma16816(acc[nt][mt], a[mt], bf[nt]);
    }
}

// ---------------------------------------------------------------------------
// Fused epilogue for chunk t: thread = (pixel, channel-of-chunk)
// ---------------------------------------------------------------------------
__device__ __forceinline__ void epilogue(int t, const __half2* ybh2,
                                         const float* xs, const float* bias_s,
                                         float* out, int tid,
                                         int b, int oy0, int ox0) {
    const int p = tid >> 1, dc = tid & 1;
    const int oyl = p >> 3, oxl = p & 7;
    const int c = t * 2 + dc;
    const float* xc = xs + c * 561 + (2 * oyl) * 17 + 2 * oxl;
    float ph[9];
    #pragma unroll
    for (int ki = 0; ki < 3; ++ki)
        #pragma unroll
        for (int kj = 0; kj < 3; ++kj) ph[ki * 3 + kj] = xc[ki * 17 + kj];
    const __half2* yb = ybh2 + p * YSTR_H2 + dc * 18;
    const float* bs = bias_s + t * NCH + dc * 36;
    float o0 = 0.f, o1 = 0.f, o2 = 0.f, o3 = 0.f;
    #pragma unroll
    for (int kk = 0; kk < 9; ++kk) {
        const float pv = ph[kk];
        float2 ya = __half22float2(yb[kk * 2]);
        float2 ybv = __half22float2(yb[kk * 2 + 1]);
        o0 += pv * fmaxf(ya.x  + bs[kk * 4],     0.f);
        o1 += pv * fmaxf(ya.y  + bs[kk * 4 + 1], 0.f);
        o2 += pv * fmaxf(ybv.x + bs[kk * 4 + 2], 0.f);
        o3 += pv * fmaxf(ybv.y + bs[kk * 4 + 3], 0.f);
    }
    const float inv9 = 1.f / 9.f;
    const size_t ob = ((size_t)(b * C_ + c) * 128 + 2 * (oy0 + oyl)) * 128
                    + 2 * (ox0 + oxl);
    *(float2*)(out + ob)       = make_float2(o0 * inv9, o1 * inv9);
    *(float2*)(out + ob + 128) = make_float2(o2 * inv9, o3 * inv9);
}

// ---------------------------------------------------------------------------
// Main fused kernel: CTA = 128 pixels (16 oy x 8 ox) of one batch image
// ---------------------------------------------------------------------------
__global__ __launch_bounds__(THREADS, 1)
void revo_hmma(const float* __restrict__ x, float* __restrict__ out) {
    extern __shared__ char smem[];
    float*  xs     = (float*)(smem + XS_OFF);
    float*  bias_s = (float*)(smem + BIAS_OFF);
    __half* feat   = (__half*)(smem + FEAT_OFF);
    float*  scr    = (float*)(smem + YB0_OFF);   // cm partials, pre-loop only
    const uint32_t sb = su32(smem);

    const int tid = threadIdx.x, lane = tid & 31, wid = tid >> 5;
    const int b = blockIdx.z, oy0 = blockIdx.y * 16, ox0 = blockIdx.x * 8;

    // stage weight chunk 0 early (overlaps x-tile load)
    stage_b(sb + B0_OFF, 0, tid);
    cpcommit();

    // ---- x tile [32][33][17], zero-padded halo + bias ----
    const float* xb = x + (size_t)b * C_ * 16384;
    for (int e = tid; e < XS_FL; e += THREADS) {
        int c = e / 561, rem = e - c * 561;
        int yy = rem / 17, xx = rem - yy * 17;
        int iy = 2 * oy0 - 1 + yy, ix = 2 * ox0 - 1 + xx;
        float v = 0.f;
        if ((unsigned)iy < 128u && (unsigned)ix < 128u) v = xb[c * 16384 + iy * 128 + ix];
        xs[e] = v;
    }
    for (int e = tid; e < 1152; e += THREADS) bias_s[e] = g_bias[e];
    __syncthreads();

    // ---- feat build, parallel over (pixel, 16-channel group) ----
    {
        const int p = tid & 127, cg = tid >> 7;   // cg = 0/1
        const int oyl = p >> 3, oxl = p & 7;
        const int pb = (2 * oyl) * 17 + 2 * oxl;
        __half* fr = feat + p * FSTR_H;
        float cm[9];
        #pragma unroll
        for (int kk = 0; kk < 9; ++kk) cm[kk] = -3.402823466e38f;
        #pragma unroll
        for (int cc = 0; cc < 16; ++cc) {
            const int c = cg * 16 + cc;
            const float* xc = xs + c * 561 + pb;
            float ph[9];
            #pragma unroll
            for (int ki = 0; ki < 3; ++ki)
                #pragma unroll
                for (int kj = 0; kj < 3; ++kj) ph[ki * 3 + kj] = xc[ki * 17 + kj];
            #pragma unroll
            for (int kk = 0; kk < 9; ++kk) cm[kk] = fmaxf(cm[kk], ph[kk]);
            #pragma unroll
            for (int j = 0; j < 3; ++j)   // max over kernel rows
                fr[9 + c * 3 + j] =
                    __float2half_rn(fmaxf(fmaxf(ph[j], ph[3 + j]), ph[6 + j]));
            #pragma unroll
            for (int i = 0; i < 3; ++i)   // max over kernel cols
                fr[105 + c * 3 + i] =
                    __float2half_rn(fmaxf(fmaxf(ph[3 * i], ph[3 * i + 1]), ph[3 * i + 2]));
        }
        #pragma unroll
        for (int kk = 0; kk < 9; ++kk) scr[p * 24 + cg * 12 + kk] = cm[kk];
    }
    __syncthreads();
    // reduce channel-max partials -> feat[0..8], zero-pad 201..207
    for (int e = tid; e < 128 * 9; e += THREADS) {
        int p = e / 9, kk = e - p * 9;
        feat[p * FSTR_H + kk] =
            __float2half_rn(fmaxf(scr[p * 24 + kk], scr[p * 24 + 12 + kk]));
    }
    if (tid < 128) {
        #pragma unroll
        for (int k = INCH; k < KH; ++k)
            feat[tid * FSTR_H + k] = __ushort_as_half(0);
    }
    __syncthreads();

    // warp tiling: 4 M-groups (32 rows) x 2 N-groups (5 / 4 n-tiles of the 9)
    const int m0 = (wid >> 1) * 32;
    const int ngrp = wid & 1;
    const int tb = ngrp ? 5 : 0;            // n-tile base
    const int g = lane >> 2, tg = lane & 3;

    // ---- pipelined main loop: phase t = stage(t+1) | GEMM(t) | epilogue(t-1)
    for (int t = 0; t < NCHUNKS; ++t) {
        if (t + 1 < NCHUNKS)
            stage_b(sb + (((t + 1) & 1) ? B1_OFF : B0_OFF), (t + 1) * NCH, tid);
        cpcommit();
        cpwait1();                 // B chunk t complete; chunk t+1 in flight

        const uint32_t bb = sb + ((t & 1) ? B1_OFF : B0_OFF);
        float acc[5][2][4];
        #pragma unroll
        for (int i = 0; i < 5; ++i)
            #pragma unroll
            for (int j = 0; j < 2; ++j)
                #pragma unroll
                for (int k = 0; k < 4; ++k) acc[i][j][k] = 0.f;

        if (ngrp == 0) gemm_chunk<5>(sb + FEAT_OFF, bb, m0, lane, acc);
        else           gemm_chunk<4>(sb + FEAT_OFF, bb + 5 * 8 * FSTR_B, m0, lane, acc);

        // C frags -> ybuf[t&1] as half2
        __half2* ybw = (__half2*)(smem + ((t & 1) ? YB1_OFF : YB0_OFF));
        const int NTloc = ngrp ? 4 : 5;
        #pragma unroll
        for (int nt = 0; nt < 5; ++nt) {
            if (nt < NTloc) {
                int h2i = (tb + nt) * 4 + tg;
                #pragma unroll
                for (int mt = 0; mt < 2; ++mt) {
                    int p0 = m0 + mt * 16 + g;
                    ybw[p0 * YSTR_H2 + h2i] =
                        __floats2half2_rn(acc[nt][mt][0], acc[nt][mt][1]);
                    ybw[(p0 + 8) * YSTR_H2 + h2i] =
                        __floats2half2_rn(acc[nt][mt][2], acc[nt][mt][3]);
                }
            }
        }

        // overlapped epilogue of previous chunk (reads the other ybuf)
        if (t > 0)
            epilogue(t - 1, (const __half2*)(smem + (((t - 1) & 1) ? YB1_OFF : YB0_OFF)),
                     xs, bias_s, out, tid, b, oy0, ox0);
        __syncthreads();
    }
    // final epilogue
    epilogue(NCHUNKS - 1,
             (const __half2*)(smem + (((NCHUNKS - 1) & 1) ? YB1_OFF : YB0_OFF)),
             xs, bias_s, out, tid, b, oy0, ox0);
}

// ---------------------------------------------------------------------------
extern "C" void kernel_launch(void* const* d_in, const int* in_sizes, int n_in,
                              void* d_out, int out_size) {
    const float* x   = (const float*)d_in[0];
    const float* cw  = (const float*)d_in[1];
    const float* gam = (const float*)d_in[2];
    const float* bet = (const float*)d_in[3];
    const float* mn  = (const float*)d_in[4];
    const float* vr  = (const float*)d_in[5];
    float* out       = (float*)d_out;

    cudaFuncSetAttribute(revo_hmma, cudaFuncAttributeMaxDynamicSharedMemorySize,
                         SMEM_BYTES);

    repack_kernel<<<1152, 128>>>(cw, gam, bet, mn, vr);
    dim3 grid(8, 4, B_);
    revo_hmma<<<grid, THREADS, SMEM_BYTES>>>(x, out);
}

// round 8
// speedup vs baseline: 1.3010x; 1.0406x over previous
#include <cuda_runtime.h>
#include <cuda_fp16.h>
#include <math.h>
#include <cstdint>

// ---------------------------------------------------------------------------
// Problem constants
// ---------------------------------------------------------------------------
#define C_      32
#define B_      8
#define INCH    201          // K*C*2 + K*K
#define KH      208          // K padded to 13 x 16 (halves)
#define KST     13           // k16 steps
#define NCH     72           // N per chunk (exactly 2 channels x 36)
#define NCHUNKS 16           // 1152 / 72
#define FSTR_H  216          // feat/B row stride in halves (27 x 16B, coprime 8)
#define FSTR_B  432          // ... in bytes
#define THREADS 256

// SMEM layout (bytes)
#define XS_FL    (32*33*17)                 // 17952 floats
#define XS_OFF   0
#define BIAS_OFF (XS_FL*4)                  // 71808
#define FEAT_OFF (BIAS_OFF + 1152*4)        // 76416
#define B0_OFF   (FEAT_OFF + 128*FSTR_B)    // 131712
#define BBYTES   (NCH*FSTR_B)               // 31104
#define B1_OFF   (B0_OFF + BBYTES)          // 162816
#define YB0_OFF  193920
#define YSTR_H2  37                         // ybuf pixel stride in half2
#define YB_BYTES (128*YSTR_H2*4)            // 18944
#define YB1_OFF  (YB0_OFF + YB_BYTES)       // 212864
#define SMEM_BYTES (YB1_OFF + YB_BYTES)     // 231808

// ---------------------------------------------------------------------------
// Static scratch (no allocations)
// ---------------------------------------------------------------------------
__device__ __half g_wh[1152 * KH];   // BN-folded fp16 weights, K-padded
__device__ float  g_bias[1152];

// ---------------------------------------------------------------------------
// PTX helpers (sm_103 BASE features only: ldmatrix / mma.sync / cp.async)
// ---------------------------------------------------------------------------
__device__ __forceinline__ uint32_t su32(const void* p) {
    uint32_t a;
    asm("{ .reg .u64 t; cvta.to.shared.u64 t, %1; cvt.u32.u64 %0, t; }" : "=r"(a) : "l"(p));
    return a;
}
__device__ __forceinline__ void ldsm4(uint32_t* r, uint32_t a) {
    asm volatile("ldmatrix.sync.aligned.m8n8.x4.shared.b16 {%0,%1,%2,%3}, [%4];"
                 : "=r"(r[0]), "=r"(r[1]), "=r"(r[2]), "=r"(r[3]) : "r"(a));
}
__device__ __forceinline__ void ldsm2(uint32_t* r, uint32_t a) {
    asm volatile("ldmatrix.sync.aligned.m8n8.x2.shared.b16 {%0,%1}, [%2];"
                 : "=r"(r[0]), "=r"(r[1]) : "r"(a));
}
__device__ __forceinline__ void mma16816(float* c, const uint32_t* a, const uint32_t* b) {
    asm volatile("mma.sync.aligned.m16n8k16.row.col.f32.f16.f16.f32 "
                 "{%0,%1,%2,%3}, {%4,%5,%6,%7}, {%8,%9}, {%0,%1,%2,%3};"
                 : "+f"(c[0]), "+f"(c[1]), "+f"(c[2]), "+f"(c[3])
                 : "r"(a[0]), "r"(a[1]), "r"(a[2]), "r"(a[3]), "r"(b[0]), "r"(b[1]));
}
__device__ __forceinline__ void cpasync16(uint32_t dst, const void* src) {
    asm volatile("cp.async.cg.shared.global [%0], [%1], 16;" :: "r"(dst), "l"(src));
}
__device__ __forceinline__ void cpcommit() { asm volatile("cp.async.commit_group;"); }
__device__ __forceinline__ void cpwait1()  { asm volatile("cp.async.wait_group 1;" ::: "memory"); }

// ---------------------------------------------------------------------------
// Repack: fold BN into conv_w, convert fp16, pad K 201->208
// ---------------------------------------------------------------------------
__global__ void repack_kernel(const float* __restrict__ w,
                              const float* __restrict__ gamma,
                              const float* __restrict__ beta,
                              const float* __restrict__ mean,
                              const float* __restrict__ var) {
    int m = blockIdx.x;
    float sc = gamma[m] * rsqrtf(var[m] + 1e-5f);
    if (threadIdx.x == 0) g_bias[m] = beta[m] - mean[m] * sc;
    for (int k = threadIdx.x; k < KH; k += blockDim.x) {
        float v = (k < INCH) ? w[m * INCH + k] * sc : 0.f;
        g_wh[m * KH + k] = __float2half_rn(v);
    }
}

// Stage one 72-row N-chunk of fp16 weights into SMEM [n][k], stride 216 halves
__device__ __forceinline__ void stage_b(uint32_t bufs, int n0, int tid) {
    for (int e = tid; e < NCH * 26; e += THREADS) {
        int r = e / 26, q = e - r * 26;
        cpasync16(bufs + r * FSTR_B + q * 16,
                  g_wh + (size_t)(n0 + r) * KH + q * 8);
    }
}

// ---------------------------------------------------------------------------
// One N-chunk GEMM with register-resident A: warp covers M=32 (2 mtiles)
// x NT n-tiles over K=208. Only B fragments touch shared memory.
// ---------------------------------------------------------------------------
template <int NT>
__device__ __forceinline__ void gemm_chunk(const uint32_t afr[KST][2][4],
                                           uint32_t bbase, int lane,
                                           float acc[][2][4]) {
    #pragma unroll
    for (int s = 0; s < KST; ++s) {
        uint32_t bf[NT][2];
        #pragma unroll
        for (int pq = 0; pq < NT / 2; ++pq) {
            uint32_t ad = bbase
                        + (uint32_t)((pq * 2 + (lane >> 4)) * 8 + (lane & 7)) * FSTR_B
                        + s * 32 + ((lane >> 3) & 1) * 16;
            uint32_t t4[4];
            ldsm4(t4, ad);
            bf[2 * pq][0] = t4[0]; bf[2 * pq][1] = t4[1];
            bf[2 * pq + 1][0] = t4[2]; bf[2 * pq + 1][1] = t4[3];
        }
        if (NT & 1) {
            uint32_t ad = bbase + (uint32_t)((NT - 1) * 8 + (lane & 7)) * FSTR_B
                        + s * 32 + ((lane >> 3) & 1) * 16;
            ldsm2(bf[NT - 1], ad);
        }
        #pragma unroll
        for (int nt = 0; nt < NT; ++nt)
            #pragma unroll
            for (int mt = 0; mt < 2; ++mt)
                mma16816(acc[nt][mt], afr[s][mt], bf[nt]);
    }
}

// ---------------------------------------------------------------------------
// Fused epilogue for chunk t: thread = (pixel, channel-of-chunk)
// ---------------------------------------------------------------------------
__device__ __forceinline__ void epilogue(int t, const __half2* ybh2,
                                         const float* xs, const float* bias_s,
                                         float* out, int tid,
                                         int b, int oy0, int ox0) {
    const int p = tid >> 1, dc = tid & 1;
    const int oyl = p >> 3, oxl = p & 7;
    const int c = t * 2 + dc;
    const float* xc = xs + c * 561 + (2 * oyl) * 17 + 2 * oxl;
    float ph[9];
    #pragma unroll
    for (int ki = 0; ki < 3; ++ki)
        #pragma unroll
        for (int kj = 0; kj < 3; ++kj) ph[ki * 3 + kj] = xc[ki * 17 + kj];
    const __half2* yb = ybh2 + p * YSTR_H2 + dc * 18;
    const float* bs = bias_s + t * NCH + dc * 36;
    float o0 = 0.f, o1 = 0.f, o2 = 0.f, o3 = 0.f;
    #pragma unroll
    for (int kk = 0; kk < 9; ++kk) {
        const float pv = ph[kk];
        float2 ya  = __half22float2(yb[kk * 2]);
        float2 ybv = __half22float2(yb[kk * 2 + 1]);
        o0 += pv * fmaxf(ya.x  + bs[kk * 4],     0.f);
        o1 += pv * fmaxf(ya.y  + bs[kk * 4 + 1], 0.f);
        o2 += pv * fmaxf(ybv.x + bs[kk * 4 + 2], 0.f);
        o3 += pv * fmaxf(ybv.y + bs[kk * 4 + 3], 0.f);
    }
    const float inv9 = 1.f / 9.f;
    const size_t ob = ((size_t)(b * C_ + c) * 128 + 2 * (oy0 + oyl)) * 128
                    + 2 * (ox0 + oxl);
    *(float2*)(out + ob)       = make_float2(o0 * inv9, o1 * inv9);
    *(float2*)(out + ob + 128) = make_float2(o2 * inv9, o3 * inv9);
}

// ---------------------------------------------------------------------------
// Main fused kernel: CTA = 128 pixels (16 oy x 8 ox) of one batch image
// ---------------------------------------------------------------------------
__global__ __launch_bounds__(THREADS, 1)
void revo_hmma(const float* __restrict__ x, float* __restrict__ out) {
    extern __shared__ char smem[];
    float*  xs     = (float*)(smem + XS_OFF);
    float*  bias_s = (float*)(smem + BIAS_OFF);
    __half* feat   = (__half*)(smem + FEAT_OFF);
    float*  scr    = (float*)(smem + YB0_OFF);   // cm partials, pre-loop only
    const uint32_t sb = su32(smem);

    const int tid = threadIdx.x, lane = tid & 31, wid = tid >> 5;
    const int b = blockIdx.z, oy0 = blockIdx.y * 16, ox0 = blockIdx.x * 8;

    // stage weight chunk 0 early (overlaps x-tile load)
    stage_b(sb + B0_OFF, 0, tid);
    cpcommit();

    // ---- x tile [32][33][17], zero-padded halo + bias ----
    const float* xb = x + (size_t)b * C_ * 16384;
    for (int e = tid; e < XS_FL; e += THREADS) {
        int c = e / 561, rem = e - c * 561;
        int yy = rem / 17, xx = rem - yy * 17;
        int iy = 2 * oy0 - 1 + yy, ix = 2 * ox0 - 1 + xx;
        float v = 0.f;
        if ((unsigned)iy < 128u && (unsigned)ix < 128u) v = xb[c * 16384 + iy * 128 + ix];
        xs[e] = v;
    }
    for (int e = tid; e < 1152; e += THREADS) bias_s[e] = g_bias[e];
    __syncthreads();

    // ---- feat build, parallel over (pixel, 16-channel group) ----
    {
        const int p = tid & 127, cg = tid >> 7;   // cg = 0/1
        const int oyl = p >> 3, oxl = p & 7;
        const int pb = (2 * oyl) * 17 + 2 * oxl;
        __half* fr = feat + p * FSTR_H;
        float cm[9];
        #pragma unroll
        for (int kk = 0; kk < 9; ++kk) cm[kk] = -3.402823466e38f;
        #pragma unroll
        for (int cc = 0; cc < 16; ++cc) {
            const int c = cg * 16 + cc;
            const float* xc = xs + c * 561 + pb;
            float ph[9];
            #pragma unroll
            for (int ki = 0; ki < 3; ++ki)
                #pragma unroll
                for (int kj = 0; kj < 3; ++kj) ph[ki * 3 + kj] = xc[ki * 17 + kj];
            #pragma unroll
            for (int kk = 0; kk < 9; ++kk) cm[kk] = fmaxf(cm[kk], ph[kk]);
            #pragma unroll
            for (int j = 0; j < 3; ++j)   // max over kernel rows
                fr[9 + c * 3 + j] =
                    __float2half_rn(fmaxf(fmaxf(ph[j], ph[3 + j]), ph[6 + j]));
            #pragma unroll
            for (int i = 0; i < 3; ++i)   // max over kernel cols
                fr[105 + c * 3 + i] =
                    __float2half_rn(fmaxf(fmaxf(ph[3 * i], ph[3 * i + 1]), ph[3 * i + 2]));
        }
        #pragma unroll
        for (int kk = 0; kk < 9; ++kk) scr[p * 24 + cg * 12 + kk] = cm[kk];
    }
    __syncthreads();
    // reduce channel-max partials -> feat[0..8], zero-pad 201..207
    for (int e = tid; e < 128 * 9; e += THREADS) {
        int p = e / 9, kk = e - p * 9;
        feat[p * FSTR_H + kk] =
            __float2half_rn(fmaxf(scr[p * 24 + kk], scr[p * 24 + 12 + kk]));
    }
    if (tid < 128) {
        #pragma unroll
        for (int k = INCH; k < KH; ++k)
            feat[tid * FSTR_H + k] = __ushort_as_half(0);
    }
    __syncthreads();

    // warp tiling: 4 M-groups (32 rows) x 2 N-groups (5 / 4 n-tiles of the 9)
    const int m0 = (wid >> 1) * 32;
    const int ngrp = wid & 1;
    const int tb = ngrp ? 5 : 0;            // n-tile base
    const int g = lane >> 2, tg = lane & 3;

    // ---- preload ALL A fragments into registers (feat invariant per chunk) --
    uint32_t afr[KST][2][4];
    #pragma unroll
    for (int s = 0; s < KST; ++s)
        #pragma unroll
        for (int mt = 0; mt < 2; ++mt)
            ldsm4(afr[s][mt],
                  sb + FEAT_OFF + (uint32_t)(m0 + mt * 16 + (lane & 15)) * FSTR_B
                  + s * 32 + (lane >> 4) * 16);

    // ---- pipelined main loop: phase t = stage(t+1) | GEMM(t) | epilogue(t-1)
    for (int t = 0; t < NCHUNKS; ++t) {
        if (t + 1 < NCHUNKS)
            stage_b(sb + (((t + 1) & 1) ? B1_OFF : B0_OFF), (t + 1) * NCH, tid);
        cpcommit();
        cpwait1();                 // B chunk t complete; chunk t+1 in flight

        const uint32_t bb = sb + ((t & 1) ? B1_OFF : B0_OFF);
        float acc[5][2][4];
        #pragma unroll
        for (int i = 0; i < 5; ++i)
            #pragma unroll
            for (int j = 0; j < 2; ++j)
                #pragma unroll
                for (int k = 0; k < 4; ++k) acc[i][j][k] = 0.f;

        if (ngrp == 0) gemm_chunk<5>(afr, bb, lane, acc);
        else           gemm_chunk<4>(afr, bb + 5 * 8 * FSTR_B, lane, acc);

        // C frags -> ybuf[t&1] as half2
        __half2* ybw = (__half2*)(smem + ((t & 1) ? YB1_OFF : YB0_OFF));
        const int NTloc = ngrp ? 4 : 5;
        #pragma unroll
        for (int nt = 0; nt < 5; ++nt) {
            if (nt < NTloc) {
                int h2i = (tb + nt) * 4 + tg;
                #pragma unroll
                for (int mt = 0; mt < 2; ++mt) {
                    int p0 = m0 + mt * 16 + g;
                    ybw[p0 * YSTR_H2 + h2i] =
                        __floats2half2_rn(acc[nt][mt][0], acc[nt][mt][1]);
                    ybw[(p0 + 8) * YSTR_H2 + h2i] =
                        __floats2half2_rn(acc[nt][mt][2], acc[nt][mt][3]);
                }
            }
        }

        // overlapped epilogue of previous chunk (reads the other ybuf)
        if (t > 0)
            epilogue(t - 1, (const __half2*)(smem + (((t - 1) & 1) ? YB1_OFF : YB0_OFF)),
                     xs, bias_s, out, tid, b, oy0, ox0);
        __syncthreads();
    }
    // final epilogue
    epilogue(NCHUNKS - 1,
             (const __half2*)(smem + (((NCHUNKS - 1) & 1) ? YB1_OFF : YB0_OFF)),
             xs, bias_s, out, tid, b, oy0, ox0);
}

// ---------------------------------------------------------------------------
extern "C" void kernel_launch(void* const* d_in, const int* in_sizes, int n_in,
                              void* d_out, int out_size) {
    const float* x   = (const float*)d_in[0];
    const float* cw  = (const float*)d_in[1];
    const float* gam = (const float*)d_in[2];
    const float* bet = (const float*)d_in[3];
    const float* mn  = (const float*)d_in[4];
    const float* vr  = (const float*)d_in[5];
    float* out       = (float*)d_out;

    cudaFuncSetAttribute(revo_hmma, cudaFuncAttributeMaxDynamicSharedMemorySize,
                         SMEM_BYTES);

    repack_kernel<<<1152, 128>>>(cw, gam, bet, mn, vr);
    dim3 grid(8, 4, B_);
    revo_hmma<<<grid, THREADS, SMEM_BYTES>>>(x, out);
}